// round 1
// baseline (speedup 1.0000x reference)
#include <cuda_runtime.h>
#include <cuda_fp16.h>

// Problem constants (from reference)
#define RESG 128
#define NI   443            // N_INTRS-1 samples per ray
#define NRAYS 4096
#define NCH  28             // 27 SH coeffs + sigma
#define VOXSTRIDE 32        // halves per voxel (padded 28 -> 32, 64B)

__constant__ float RADIUS_C = 1.3f;
#define STEPF (1.3f / 128.0f)      // 2*R/RES/2

// Scratch: transposed fp16 grid, voxel-major [z][y][x][32 halves] = 134 MB.
// __device__ global (module-load allocation) — the sanctioned scratch mechanism.
__device__ __half2 g_grid2[(size_t)RESG * RESG * RESG * (VOXSTRIDE / 2)];

// ---------------------------------------------------------------------------
// Kernel 1: transpose + fp32->fp16 convert.
// One block per (z,y) row. Coalesced 512B reads per channel, smem tile,
// contiguous 56B half2 writes per voxel.
// ---------------------------------------------------------------------------
__global__ void __launch_bounds__(128) xpose_kernel(const float* __restrict__ src) {
    __shared__ float s[128][29];   // pad 29 -> conflict-free column access
    const int zy  = blockIdx.x;    // 0 .. 128*128-1
    const int tid = threadIdx.x;   // 128 threads, tid = x for reads

    const float* p = src + (size_t)zy * RESG + tid;
#pragma unroll
    for (int c = 0; c < NCH; ++c)
        s[tid][c] = p[(size_t)c * (RESG * RESG * RESG)];
    __syncthreads();

    // Write: lane h (0..13) writes channel pair (2h, 2h+1) of voxel x.
    const int h  = tid & 15;
    const int xs = tid >> 4;       // 8 voxels per iteration
#pragma unroll
    for (int it = 0; it < 16; ++it) {
        int x = xs + it * 8;
        if (h < 14) {
            __half2 v = __floats2half2_rn(s[x][2 * h], s[x][2 * h + 1]);
            g_grid2[((size_t)zy * RESG + x) * (VOXSTRIDE / 2) + h] = v;
        }
    }
}

// ---------------------------------------------------------------------------
// Kernel 2: ray march. One warp per ray, one lane per channel (lanes 0..27).
// Per sample: 8 coalesced corner loads (each 56B contiguous -> 1 L1 wavefront),
// per-lane trilerp, segmented shuffle-reduce for the 3 SH color dots,
// warp-uniform alpha/transmittance accumulation.
// ---------------------------------------------------------------------------
__global__ void __launch_bounds__(128) march_kernel(const float* __restrict__ rays_o,
                                                    const float* __restrict__ rays_d,
                                                    float* __restrict__ out) {
    const int warp = (blockIdx.x * blockDim.x + threadIdx.x) >> 5;
    const int lane = threadIdx.x & 31;
    if (warp >= NRAYS) return;

    const float R = RADIUS_C;
    const float rox = rays_o[warp * 3 + 0];
    const float roy = rays_o[warp * 3 + 1];
    const float roz = rays_o[warp * 3 + 2];
    const float rdx = rays_d[warp * 3 + 0];
    const float rdy = rays_d[warp * 3 + 1];
    const float rdz = rays_d[warp * 3 + 2];

    // Entry t: max over axes of min((R-o)/d, (-R-o)/d)
    float mx = fminf((R - rox) / rdx, (-R - rox) / rdx);
    float my = fminf((R - roy) / rdy, (-R - roy) / rdy);
    float mz = fminf((R - roz) / rdz, (-R - roz) / rdz);
    const float start = fmaxf(fmaxf(mx, my), mz);

    const float nrm = sqrtf(rdx * rdx + rdy * rdy + rdz * rdz);
    const float ds  = STEPF * nrm;            // dists (constant along ray)

    // Grid-space ray:  u = og + t*dg ,  u in [0,127] inside box
    const float SC = 63.5f / R;
    const float ogx = fmaf(rox, SC, 63.5f);
    const float ogy = fmaf(roy, SC, 63.5f);
    const float ogz = fmaf(roz, SC, 63.5f);
    const float dgx = rdx * SC, dgy = rdy * SC, dgz = rdz * SC;

    // Per-lane SH basis coefficient (channel c = color*9 + k, k = c % 9)
    const int cl = lane < 27 ? lane : 27;     // lanes 28..31 alias sigma channel
    const int k  = cl % 9;
    const float x = rdx, y = rdy, z = rdz;
    float mysh;
    switch (k) {
        case 0: mysh = 0.28209479177387814f; break;
        case 1: mysh = -0.4886025119029199f * y; break;
        case 2: mysh =  0.4886025119029199f * z; break;
        case 3: mysh = -0.4886025119029199f * x; break;
        case 4: mysh =  1.0925484305920792f * x * y; break;
        case 5: mysh = -1.0925484305920792f * y * z; break;
        case 6: mysh =  0.31539156525252005f * (2.0f * z * z - x * x - y * y); break;
        case 7: mysh = -1.0925484305920792f * x * z; break;
        default: mysh = 0.5462742152960396f * (x * x - y * y); break;
    }

    const __half* __restrict__ gh = (const __half*)g_grid2;

    float T = 1.0f;
    float acc = 0.0f;   // lanes 0/9/18 accumulate color 0/1/2
    bool entered = false;

    for (int i = 0; i < NI; ++i) {
        const float t  = fmaf((float)i, STEPF, start);
        const float ux = fmaf(t, dgx, ogx);
        const float uy = fmaf(t, dgy, ogy);
        const float uz = fmaf(t, dgz, ogz);
        // warp-uniform mask (strict, matching reference pts in (-R, R))
        const bool inb = (ux > 0.0f) & (ux < 127.0f) &
                         (uy > 0.0f) & (uy < 127.0f) &
                         (uz > 0.0f) & (uz < 127.0f);
        if (!inb) {
            if (entered) break;   // convex box: once exited, stays out
            continue;
        }
        entered = true;

        const float flx = floorf(ux), fly = floorf(uy), flz = floorf(uz);
        const int ix = (int)flx, iy = (int)fly, iz = (int)flz;
        const float fx = ux - flx, fy = uy - fly, fz = uz - flz;

        const unsigned dxi = (ix < 127) ? VOXSTRIDE : 0u;
        const unsigned dyi = (iy < 127) ? (RESG * VOXSTRIDE) : 0u;
        const unsigned dzi = (iz < 127) ? (RESG * RESG * VOXSTRIDE) : 0u;
        const unsigned b = ((unsigned)(iz * RESG + iy) * RESG + (unsigned)ix) * VOXSTRIDE
                           + (unsigned)cl;

        // 8 corner loads: each warp-coalesced into one 64B-aligned voxel block
        const float v000 = __half2float(gh[b]);
        const float v001 = __half2float(gh[b + dxi]);
        const float v010 = __half2float(gh[b + dyi]);
        const float v011 = __half2float(gh[b + dyi + dxi]);
        const float v100 = __half2float(gh[b + dzi]);
        const float v101 = __half2float(gh[b + dzi + dxi]);
        const float v110 = __half2float(gh[b + dzi + dyi]);
        const float v111 = __half2float(gh[b + dzi + dyi + dxi]);

        const float gx = 1.0f - fx, gy = 1.0f - fy, gz = 1.0f - fz;
        const float a00 = gz * gy, a01 = gz * fy, a10 = fz * gy, a11 = fz * fy;
        float itp;
        itp = v000 * (a00 * gx);
        itp = fmaf(v001, a00 * fx, itp);
        itp = fmaf(v010, a01 * gx, itp);
        itp = fmaf(v011, a01 * fx, itp);
        itp = fmaf(v100, a10 * gx, itp);
        itp = fmaf(v101, a10 * fx, itp);
        itp = fmaf(v110, a11 * gx, itp);
        itp = fmaf(v111, a11 * fx, itp);

        // Segmented 9-lane reduction: lanes 0/9/18 end with their color dot
        const float wv = itp * mysh;
        float r = wv;
        r += __shfl_down_sync(0xffffffffu, r, 1);
        r += __shfl_down_sync(0xffffffffu, r, 2);
        r += __shfl_down_sync(0xffffffffu, r, 4);
        r += __shfl_down_sync(0xffffffffu, wv, 8);

        const float sg    = __shfl_sync(0xffffffffu, itp, 27);   // sigma interp
        const float sigma = fmaxf(sg, 0.0f);
        const float e     = __expf(-sigma * ds);
        const float al    = 1.0f - e;
        // sigmoid of this lane's r (only meaningful on lanes 0/9/18)
        const float sgm = __frcp_rn(1.0f + __expf(-r));
        acc = fmaf(T * al, sgm, acc);
        T *= e;
    }

    const float a0 = __shfl_sync(0xffffffffu, acc, 0);
    const float a1 = __shfl_sync(0xffffffffu, acc, 9);
    const float a2 = __shfl_sync(0xffffffffu, acc, 18);
    if (lane == 0) {
        out[warp * 3 + 0] = a0 + T;   // + background term (1 - sum abs_light) folded: = T_final
        out[warp * 3 + 1] = a1 + T;
        out[warp * 3 + 2] = a2 + T;
    }
}

extern "C" void kernel_launch(void* const* d_in, const int* in_sizes, int n_in,
                              void* d_out, int out_size) {
    const float* rays_o = (const float*)d_in[0];
    const float* rays_d = (const float*)d_in[1];
    const float* data   = (const float*)d_in[2];
    float* out = (float*)d_out;

    xpose_kernel<<<RESG * RESG, 128>>>(data);
    march_kernel<<<NRAYS / 4, 128>>>(rays_o, rays_d, out);
}

// round 2
// speedup vs baseline: 1.3173x; 1.3173x over previous
#include <cuda_runtime.h>
#include <cuda_fp16.h>

#define RESG 128
#define NI   443            // samples per ray
#define NRAYS 4096
#define NCH  28             // 27 SH + sigma (source layout)
#define VH2  16             // half2 per voxel (32 halves, 64B)

#define STEPF (1.3f / 128.0f)
#define RADF  1.3f

// Transposed fp16 grid, voxel-major, slots: [c0 k0..8,pad][c1 ...][c2 ...][sigma][pad]
__device__ __half2 g_grid2[(size_t)RESG * RESG * RESG * VH2];

// ---------------------------------------------------------------------------
// Kernel 1: transpose fp32 channel-major -> fp16 voxel-major (padded slots).
// ---------------------------------------------------------------------------
__global__ void __launch_bounds__(128) xpose_kernel(const float* __restrict__ src) {
    __shared__ float s[128][29];
    const int zy  = blockIdx.x;
    const int tid = threadIdx.x;          // = x for reads, = voxel for writes

    const float* p = src + (size_t)zy * RESG + tid;
#pragma unroll
    for (int c = 0; c < NCH; ++c)
        s[tid][c] = p[(size_t)c * (RESG * RESG * RESG)];
    __syncthreads();

    // Each thread packs its own voxel: 16 half2 = 64B, written as 4x uint4.
    __half2 v[16];
#pragma unroll
    for (int h = 0; h < 16; ++h) {
        int s0 = 2 * h, s1 = 2 * h + 1;
        float f0, f1;
        // slot -> source channel (color*9 + k), pads/sigma handled explicitly
        f0 = (s0 < 30) ? ((s0 % 10 == 9) ? 0.0f : s[tid][(s0 / 10) * 9 + (s0 % 10)])
                       : ((s0 == 30) ? s[tid][27] : 0.0f);
        f1 = (s1 < 30) ? ((s1 % 10 == 9) ? 0.0f : s[tid][(s1 / 10) * 9 + (s1 % 10)])
                       : ((s1 == 30) ? s[tid][27] : 0.0f);
        v[h] = __floats2half2_rn(f0, f1);
    }
    uint4* dst = (uint4*)&g_grid2[((size_t)zy * RESG + tid) * VH2];
    const uint4* sv = (const uint4*)v;
#pragma unroll
    for (int q = 0; q < 4; ++q) dst[q] = sv[q];
}

// ---------------------------------------------------------------------------
// Kernel 2: ray march. Warp = 1 ray, half-warp = 1 sample, lane = 2 channels.
// ---------------------------------------------------------------------------
__global__ void __launch_bounds__(128) march_kernel(const float* __restrict__ rays_o,
                                                    const float* __restrict__ rays_d,
                                                    float* __restrict__ out) {
    const int warp = (blockIdx.x * blockDim.x + threadIdx.x) >> 5;
    const int lane = threadIdx.x & 31;
    if (warp >= NRAYS) return;
    const int   l16   = lane & 15;
    const float halff = (lane >= 16) ? 1.0f : 0.0f;

    const float rox = rays_o[warp * 3 + 0];
    const float roy = rays_o[warp * 3 + 1];
    const float roz = rays_o[warp * 3 + 2];
    const float rdx = rays_d[warp * 3 + 0];
    const float rdy = rays_d[warp * 3 + 1];
    const float rdz = rays_d[warp * 3 + 2];

    float mx = fminf((RADF - rox) / rdx, (-RADF - rox) / rdx);
    float my = fminf((RADF - roy) / rdy, (-RADF - roy) / rdy);
    float mz = fminf((RADF - roz) / rdz, (-RADF - roz) / rdz);
    const float start = fmaxf(fmaxf(mx, my), mz);

    const float nrm = sqrtf(rdx * rdx + rdy * rdy + rdz * rdz);
    const float ds  = STEPF * nrm;

    // grid-space: u = p0 + fi * sv
    const float SC = 63.5f / RADF;
    const float p0x = fmaf(fmaf(rox, SC, 63.5f) == 0 ? 0 : 1.0f, 0.0f, fmaf(start, rdx * SC, fmaf(rox, SC, 63.5f)));
    const float p0y = fmaf(start, rdy * SC, fmaf(roy, SC, 63.5f));
    const float p0z = fmaf(start, rdz * SC, fmaf(roz, SC, 63.5f));
    const float svx = STEPF * rdx * SC, svy = STEPF * rdy * SC, svz = STEPF * rdz * SC;

    // SH basis (9 values), per-lane pair of weights
    const float x = rdx, y = rdy, z = rdz;
    float shv[9];
    shv[0] = 0.28209479177387814f;
    shv[1] = -0.4886025119029199f * y;
    shv[2] =  0.4886025119029199f * z;
    shv[3] = -0.4886025119029199f * x;
    shv[4] =  1.0925484305920792f * x * y;
    shv[5] = -1.0925484305920792f * y * z;
    shv[6] =  0.31539156525252005f * (2.0f * z * z - x * x - y * y);
    shv[7] = -1.0925484305920792f * x * z;
    shv[8] =  0.5462742152960396f * (x * x - y * y);
    float shx = 0.0f, shy = 0.0f;
    if (l16 < 15) {
        int j0 = 2 * (l16 % 5);
        shx = shv[j0];
        shy = (j0 + 1 < 9) ? shv[j0 + 1] : 0.0f;
    }

    const __half2* __restrict__ g2 = g_grid2;

    float T = 1.0f;
    float acc = 0.0f;
    bool entered = false;

    for (int i = 0; i < NI; i += 2) {
        const float fi = (float)i + halff;
        float ux = fmaf(fi, svx, p0x);
        float uy = fmaf(fi, svy, p0y);
        float uz = fmaf(fi, svz, p0z);
        bool inb = (ux > 0.0f) & (ux < 127.0f) &
                   (uy > 0.0f) & (uy < 127.0f) &
                   (uz > 0.0f) & (uz < 127.0f) &
                   (fi < (float)NI - 0.5f);
        const unsigned act = __ballot_sync(0xffffffffu, inb);
        if (act == 0) {
            if (entered) break;
            continue;
        }
        entered = true;
        if (!inb) { ux = 1.0f; uy = 1.0f; uz = 1.0f; }

        const float flx = floorf(ux), fly = floorf(uy), flz = floorf(uz);
        const int ix = (int)flx, iy = (int)fly, iz = (int)flz;
        const float fx = ux - flx, fy = uy - fly, fz = uz - flz;

        const unsigned dxi = (ix < 127) ? VH2 : 0u;
        const unsigned dyi = (iy < 127) ? (RESG * VH2) : 0u;
        const unsigned dzi = (iz < 127) ? (RESG * RESG * VH2) : 0u;
        const unsigned vb = ((unsigned)(iz * RESG + iy) * RESG + (unsigned)ix) * VH2
                            + (unsigned)l16;

        const float2 f000 = __half22float2(g2[vb]);
        const float2 f001 = __half22float2(g2[vb + dxi]);
        const float2 f010 = __half22float2(g2[vb + dyi]);
        const float2 f011 = __half22float2(g2[vb + dyi + dxi]);
        const float2 f100 = __half22float2(g2[vb + dzi]);
        const float2 f101 = __half22float2(g2[vb + dzi + dxi]);
        const float2 f110 = __half22float2(g2[vb + dzi + dyi]);
        const float2 f111 = __half22float2(g2[vb + dzi + dyi + dxi]);

        const float gx = 1.0f - fx, gy = 1.0f - fy, gz = 1.0f - fz;
        const float a00 = gz * gy, a01 = gz * fy, a10 = fz * gy, a11 = fz * fy;
        const float w0 = a00 * gx, w1 = a00 * fx, w2 = a01 * gx, w3 = a01 * fx;
        const float w4 = a10 * gx, w5 = a10 * fx, w6 = a11 * gx, w7 = a11 * fx;

        float ipx, ipy;
        ipx = f000.x * w0;                ipy = f000.y * w0;
        ipx = fmaf(f001.x, w1, ipx);      ipy = fmaf(f001.y, w1, ipy);
        ipx = fmaf(f010.x, w2, ipx);      ipy = fmaf(f010.y, w2, ipy);
        ipx = fmaf(f011.x, w3, ipx);      ipy = fmaf(f011.y, w3, ipy);
        ipx = fmaf(f100.x, w4, ipx);      ipy = fmaf(f100.y, w4, ipy);
        ipx = fmaf(f101.x, w5, ipx);      ipy = fmaf(f101.y, w5, ipy);
        ipx = fmaf(f110.x, w6, ipx);      ipy = fmaf(f110.y, w6, ipy);
        ipx = fmaf(f111.x, w7, ipx);      ipy = fmaf(f111.y, w7, ipy);

        // per-lane pair dot, then 5-lane segmented sum (colors at l16 = 0,5,10)
        const float wv = fmaf(ipx, shx, ipy * shy);
        float r = wv;
        r += __shfl_down_sync(0xffffffffu, r, 1, 16);
        r += __shfl_down_sync(0xffffffffu, r, 2, 16);
        r += __shfl_down_sync(0xffffffffu, wv, 4, 16);

        // sigma lives in lane 15's ipx (per half-warp)
        const float sg = __shfl_sync(0xffffffffu, ipx, 15, 16);
        float e;
        if (inb) {
            const float sigma = fmaxf(sg, 0.0f);
            e = __expf(-sigma * ds);
        } else {
            e = 1.0f;
        }

        const float eA = __shfl_sync(0xffffffffu, e, 0);    // sample i
        const float eB = __shfl_sync(0xffffffffu, e, 16);   // sample i+1
        const float factor = (lane < 16) ? T * (1.0f - eA) : T * eA * (1.0f - eB);
        const float sgm = __frcp_rn(1.0f + __expf(-r));
        acc = fmaf(factor, sgm, acc);
        T = T * eA * eB;
    }

    // colors: sample-even at lanes 0/5/10, sample-odd at 16/21/26
    const float c0 = __shfl_sync(0xffffffffu, acc, 0)  + __shfl_sync(0xffffffffu, acc, 16);
    const float c1 = __shfl_sync(0xffffffffu, acc, 5)  + __shfl_sync(0xffffffffu, acc, 21);
    const float c2 = __shfl_sync(0xffffffffu, acc, 10) + __shfl_sync(0xffffffffu, acc, 26);
    if (lane == 0) {
        out[warp * 3 + 0] = c0 + T;
        out[warp * 3 + 1] = c1 + T;
        out[warp * 3 + 2] = c2 + T;
    }
}

extern "C" void kernel_launch(void* const* d_in, const int* in_sizes, int n_in,
                              void* d_out, int out_size) {
    const float* rays_o = (const float*)d_in[0];
    const float* rays_d = (const float*)d_in[1];
    const float* data   = (const float*)d_in[2];
    float* out = (float*)d_out;

    xpose_kernel<<<RESG * RESG, 128>>>(data);
    march_kernel<<<NRAYS / 4, 128>>>(rays_o, rays_d, out);
}

// round 3
// speedup vs baseline: 1.3993x; 1.0623x over previous
#include <cuda_runtime.h>
#include <cuda_fp16.h>

#define RESG 128
#define NI   443            // samples per ray
#define NRAYS 4096
#define NCH  28             // 27 SH + sigma (source layout)
#define VH2  16             // half2 per voxel (32 halves, 64B)
#define NSEG 4
#define SEGL 112            // even, NSEG*SEGL >= NI

#define STEPF (1.3f / 128.0f)
#define RADF  1.3f

// Transposed fp16 grid, voxel-major, slots: [c0 k0..8,pad][c1 ...][c2 ...][sigma][pad]
__device__ __half2 g_grid2[(size_t)RESG * RESG * RESG * VH2];
// Per-(ray,segment) partials: {c0, c1, c2, T}
__device__ float4 g_part[NRAYS * NSEG];

// ---------------------------------------------------------------------------
// Kernel 1: transpose fp32 channel-major -> fp16 voxel-major (padded slots).
// ---------------------------------------------------------------------------
__global__ void __launch_bounds__(128) xpose_kernel(const float* __restrict__ src) {
    __shared__ float s[128][29];
    const int zy  = blockIdx.x;
    const int tid = threadIdx.x;

    const float* p = src + (size_t)zy * RESG + tid;
#pragma unroll
    for (int c = 0; c < NCH; ++c)
        s[tid][c] = p[(size_t)c * (RESG * RESG * RESG)];
    __syncthreads();

    __half2 v[16];
#pragma unroll
    for (int h = 0; h < 16; ++h) {
        int s0 = 2 * h, s1 = 2 * h + 1;
        float f0, f1;
        f0 = (s0 < 30) ? ((s0 % 10 == 9) ? 0.0f : s[tid][(s0 / 10) * 9 + (s0 % 10)])
                       : ((s0 == 30) ? s[tid][27] : 0.0f);
        f1 = (s1 < 30) ? ((s1 % 10 == 9) ? 0.0f : s[tid][(s1 / 10) * 9 + (s1 % 10)])
                       : ((s1 == 30) ? s[tid][27] : 0.0f);
        v[h] = __floats2half2_rn(f0, f1);
    }
    uint4* dst = (uint4*)&g_grid2[((size_t)zy * RESG + tid) * VH2];
    const uint4* sv = (const uint4*)v;
#pragma unroll
    for (int q = 0; q < 4; ++q) dst[q] = sv[q];
}

// ---------------------------------------------------------------------------
// Kernel 2: ray march, split-K over transmittance.
// Warp = (ray, segment). Half-warp = 1 sample. Lane = 2 channels.
// ---------------------------------------------------------------------------
__global__ void __launch_bounds__(128) march_kernel(const float* __restrict__ rays_o,
                                                    const float* __restrict__ rays_d) {
    const int wid  = (blockIdx.x * blockDim.x + threadIdx.x) >> 5;
    const int lane = threadIdx.x & 31;
    const int ray  = wid >> 2;
    const int seg  = wid & 3;
    if (ray >= NRAYS) return;
    const int   l16   = lane & 15;
    const float halff = (lane >= 16) ? 1.0f : 0.0f;

    const float rox = rays_o[ray * 3 + 0];
    const float roy = rays_o[ray * 3 + 1];
    const float roz = rays_o[ray * 3 + 2];
    const float rdx = rays_d[ray * 3 + 0];
    const float rdy = rays_d[ray * 3 + 1];
    const float rdz = rays_d[ray * 3 + 2];

    const float opx = (RADF - rox) / rdx, onx = (-RADF - rox) / rdx;
    const float opy = (RADF - roy) / rdy, ony = (-RADF - roy) / rdy;
    const float opz = (RADF - roz) / rdz, onz = (-RADF - roz) / rdz;
    const float start  = fmaxf(fmaxf(fminf(opx, onx), fminf(opy, ony)), fminf(opz, onz));
    const float t_exit = fminf(fminf(fmaxf(opx, onx), fmaxf(opy, ony)), fmaxf(opz, onz));

    // segment sample range, clipped to analytic exit (+2 safety margin)
    const int seg_lo = seg * SEGL;
    int seg_hi = min(seg_lo + SEGL, NI);
    const int iend = (int)floorf((t_exit - start) * (1.0f / STEPF)) + 2;
    seg_hi = min(seg_hi, iend);
    if (seg_lo >= seg_hi) {
        if (lane == 0) g_part[ray * NSEG + seg] = make_float4(0.0f, 0.0f, 0.0f, 1.0f);
        return;
    }

    const float nrm = sqrtf(rdx * rdx + rdy * rdy + rdz * rdz);
    const float ds  = STEPF * nrm;

    // grid-space: u = p0 + fi * sv
    const float SC = 63.5f / RADF;
    const float p0x = fmaf(start, rdx * SC, fmaf(rox, SC, 63.5f));
    const float p0y = fmaf(start, rdy * SC, fmaf(roy, SC, 63.5f));
    const float p0z = fmaf(start, rdz * SC, fmaf(roz, SC, 63.5f));
    const float svx = STEPF * rdx * SC, svy = STEPF * rdy * SC, svz = STEPF * rdz * SC;

    // SH basis, per-lane pair of weights
    const float x = rdx, y = rdy, z = rdz;
    float shv[9];
    shv[0] = 0.28209479177387814f;
    shv[1] = -0.4886025119029199f * y;
    shv[2] =  0.4886025119029199f * z;
    shv[3] = -0.4886025119029199f * x;
    shv[4] =  1.0925484305920792f * x * y;
    shv[5] = -1.0925484305920792f * y * z;
    shv[6] =  0.31539156525252005f * (2.0f * z * z - x * x - y * y);
    shv[7] = -1.0925484305920792f * x * z;
    shv[8] =  0.5462742152960396f * (x * x - y * y);
    float shx = 0.0f, shy = 0.0f;
    if (l16 < 15) {
        int j0 = 2 * (l16 % 5);
        shx = shv[j0];
        shy = (j0 + 1 < 9) ? shv[j0 + 1] : 0.0f;
    }

    const __half2* __restrict__ g2 = g_grid2;

    float T = 1.0f;
    float acc = 0.0f;

    for (int i = seg_lo; i < seg_hi; i += 2) {
        const float fi = (float)i + halff;
        float ux = fmaf(fi, svx, p0x);
        float uy = fmaf(fi, svy, p0y);
        float uz = fmaf(fi, svz, p0z);
        const bool inb = (ux > 0.0f) & (ux < 127.0f) &
                         (uy > 0.0f) & (uy < 127.0f) &
                         (uz > 0.0f) & (uz < 127.0f) &
                         (fi < (float)NI - 0.5f);
        if (!inb) { ux = 1.0f; uy = 1.0f; uz = 1.0f; }

        const float flx = floorf(ux), fly = floorf(uy), flz = floorf(uz);
        const int ix = (int)flx, iy = (int)fly, iz = (int)flz;
        const float fx = ux - flx, fy = uy - fly, fz = uz - flz;

        const unsigned dxi = (ix < 127) ? VH2 : 0u;
        const unsigned dyi = (iy < 127) ? (RESG * VH2) : 0u;
        const unsigned dzi = (iz < 127) ? (RESG * RESG * VH2) : 0u;
        const unsigned vb = ((unsigned)(iz * RESG + iy) * RESG + (unsigned)ix) * VH2
                            + (unsigned)l16;

        const float2 f000 = __half22float2(g2[vb]);
        const float2 f001 = __half22float2(g2[vb + dxi]);
        const float2 f010 = __half22float2(g2[vb + dyi]);
        const float2 f011 = __half22float2(g2[vb + dyi + dxi]);
        const float2 f100 = __half22float2(g2[vb + dzi]);
        const float2 f101 = __half22float2(g2[vb + dzi + dxi]);
        const float2 f110 = __half22float2(g2[vb + dzi + dyi]);
        const float2 f111 = __half22float2(g2[vb + dzi + dyi + dxi]);

        const float gx = 1.0f - fx, gy = 1.0f - fy, gz = 1.0f - fz;
        const float a00 = gz * gy, a01 = gz * fy, a10 = fz * gy, a11 = fz * fy;
        const float w0 = a00 * gx, w1 = a00 * fx, w2 = a01 * gx, w3 = a01 * fx;
        const float w4 = a10 * gx, w5 = a10 * fx, w6 = a11 * gx, w7 = a11 * fx;

        float ipx, ipy;
        ipx = f000.x * w0;                ipy = f000.y * w0;
        ipx = fmaf(f001.x, w1, ipx);      ipy = fmaf(f001.y, w1, ipy);
        ipx = fmaf(f010.x, w2, ipx);      ipy = fmaf(f010.y, w2, ipy);
        ipx = fmaf(f011.x, w3, ipx);      ipy = fmaf(f011.y, w3, ipy);
        ipx = fmaf(f100.x, w4, ipx);      ipy = fmaf(f100.y, w4, ipy);
        ipx = fmaf(f101.x, w5, ipx);      ipy = fmaf(f101.y, w5, ipy);
        ipx = fmaf(f110.x, w6, ipx);      ipy = fmaf(f110.y, w6, ipy);
        ipx = fmaf(f111.x, w7, ipx);      ipy = fmaf(f111.y, w7, ipy);

        // per-lane pair dot, then 5-lane segmented sum (colors at l16 = 0,5,10)
        const float wv = fmaf(ipx, shx, ipy * shy);
        float r = wv;
        r += __shfl_down_sync(0xffffffffu, r, 1, 16);
        r += __shfl_down_sync(0xffffffffu, r, 2, 16);
        r += __shfl_down_sync(0xffffffffu, wv, 4, 16);

        // sigma in lane 15's ipx (per half-warp); mask via sigma=0 -> e=1
        const float sg    = __shfl_sync(0xffffffffu, ipx, 15, 16);
        const float sigma = inb ? fmaxf(sg, 0.0f) : 0.0f;
        const float e     = __expf(-sigma * ds);

        const float eA = __shfl_sync(0xffffffffu, e, 0);    // sample i
        const float eB = __shfl_sync(0xffffffffu, e, 16);   // sample i+1
        const float factor = (lane < 16) ? T * (1.0f - eA) : T * eA * (1.0f - eB);
        const float sgm = __frcp_rn(1.0f + __expf(-r));
        acc = fmaf(factor, sgm, acc);
        T = T * eA * eB;
    }

    const float c0 = __shfl_sync(0xffffffffu, acc, 0)  + __shfl_sync(0xffffffffu, acc, 16);
    const float c1 = __shfl_sync(0xffffffffu, acc, 5)  + __shfl_sync(0xffffffffu, acc, 21);
    const float c2 = __shfl_sync(0xffffffffu, acc, 10) + __shfl_sync(0xffffffffu, acc, 26);
    if (lane == 0) g_part[ray * NSEG + seg] = make_float4(c0, c1, c2, T);
}

// ---------------------------------------------------------------------------
// Kernel 3: combine segment partials:  acc += T_prefix * acc_s ; T *= T_s
// ---------------------------------------------------------------------------
__global__ void __launch_bounds__(128) combine_kernel(float* __restrict__ out) {
    const int r = blockIdx.x * blockDim.x + threadIdx.x;
    if (r >= NRAYS) return;
    float c0 = 0.0f, c1 = 0.0f, c2 = 0.0f, T = 1.0f;
#pragma unroll
    for (int s = 0; s < NSEG; ++s) {
        const float4 p = g_part[r * NSEG + s];
        c0 = fmaf(T, p.x, c0);
        c1 = fmaf(T, p.y, c1);
        c2 = fmaf(T, p.z, c2);
        T *= p.w;
    }
    out[r * 3 + 0] = c0 + T;
    out[r * 3 + 1] = c1 + T;
    out[r * 3 + 2] = c2 + T;
}

extern "C" void kernel_launch(void* const* d_in, const int* in_sizes, int n_in,
                              void* d_out, int out_size) {
    const float* rays_o = (const float*)d_in[0];
    const float* rays_d = (const float*)d_in[1];
    const float* data   = (const float*)d_in[2];
    float* out = (float*)d_out;

    xpose_kernel<<<RESG * RESG, 128>>>(data);
    march_kernel<<<NRAYS * NSEG / 4, 128>>>(rays_o, rays_d);
    combine_kernel<<<NRAYS / 128, 128>>>(out);
}

// round 5
// speedup vs baseline: 1.7222x; 1.2307x over previous
#include <cuda_runtime.h>
#include <cuda_fp16.h>

#define RESG 128
#define NI   443
#define NRAYS 4096
#define NCH  28
#define NSEG 4
#define SEGL 112

#define STEPF (1.3f / 128.0f)
#define RADF  1.3f

// fp16 voxel-major grid. 32 halves/voxel:
//  slots 0-7: c0 k0-7 | 8-15: c1 k0-7 | 16-23: c2 k0-7 | 24:c0k8 25:c1k8 26:c2k8 27:sigma | 28-31 pad
__device__ __half2 g_grid2[(size_t)RESG * RESG * RESG * 16];
__device__ float4 g_part[NRAYS * NSEG];

// ---------------------------------------------------------------------------
// Kernel 1: transpose fp32 channel-major -> fp16 voxel-major (new slot map).
// ---------------------------------------------------------------------------
__global__ void __launch_bounds__(128) xpose_kernel(const float* __restrict__ src) {
    __shared__ float s[NCH * RESG];
    const int zy  = blockIdx.x;
    const int tid = threadIdx.x;

    // load: 28 channels x 32 float4 = 896 float4, 7 per thread, coalesced
    const float4* src4 = (const float4*)src;
#pragma unroll
    for (int it = 0; it < 7; ++it) {
        const int idx = tid + 128 * it;
        const int c  = idx >> 5;
        const int x4 = idx & 31;
        float4 v = src4[(size_t)c * (RESG * RESG * RESG / 4) + (size_t)zy * 32 + x4];
        *(float4*)&s[c * RESG + 4 * x4] = v;
    }
    __syncthreads();

    // pack: thread = voxel x
    float val[32];
#pragma unroll
    for (int sl = 0; sl < 32; ++sl) {
        int ch;
        if (sl < 24)       ch = (sl >> 3) * 9 + (sl & 7);
        else if (sl == 24) ch = 8;
        else if (sl == 25) ch = 17;
        else if (sl == 26) ch = 26;
        else if (sl == 27) ch = 27;
        else               ch = -1;
        val[sl] = (ch >= 0) ? s[ch * RESG + tid] : 0.0f;
    }
    __half2 v2[16];
#pragma unroll
    for (int h = 0; h < 16; ++h) v2[h] = __floats2half2_rn(val[2 * h], val[2 * h + 1]);

    uint4* dst = (uint4*)&g_grid2[((size_t)zy * RESG + tid) * 16];
    const uint4* sv = (const uint4*)v2;
#pragma unroll
    for (int q = 0; q < 4; ++q) dst[q] = sv[q];
}

// ---------------------------------------------------------------------------
// Kernel 2: ray march. Warp = (ray, segment). Quarter-warp = 1 sample.
// Lane = 4 channels (2x half2). Trilerp in HFMA2.
// ---------------------------------------------------------------------------
__global__ void __launch_bounds__(128) march_kernel(const float* __restrict__ rays_o,
                                                    const float* __restrict__ rays_d) {
    const int wid  = (blockIdx.x * blockDim.x + threadIdx.x) >> 5;
    const int lane = threadIdx.x & 31;
    const int ray  = wid >> 2;
    const int seg  = wid & 3;
    if (ray >= NRAYS) return;
    const int l8 = lane & 7;
    const float qf = (float)(lane >> 3);

    const float rox = rays_o[ray * 3 + 0];
    const float roy = rays_o[ray * 3 + 1];
    const float roz = rays_o[ray * 3 + 2];
    const float rdx = rays_d[ray * 3 + 0];
    const float rdy = rays_d[ray * 3 + 1];
    const float rdz = rays_d[ray * 3 + 2];

    const float opx = (RADF - rox) / rdx, onx = (-RADF - rox) / rdx;
    const float opy = (RADF - roy) / rdy, ony = (-RADF - roy) / rdy;
    const float opz = (RADF - roz) / rdz, onz = (-RADF - roz) / rdz;
    const float start  = fmaxf(fmaxf(fminf(opx, onx), fminf(opy, ony)), fminf(opz, onz));
    const float t_exit = fminf(fminf(fmaxf(opx, onx), fmaxf(opy, ony)), fmaxf(opz, onz));

    const int seg_lo = seg * SEGL;
    int seg_hi = min(seg_lo + SEGL, NI);
    const int iend = (int)floorf((t_exit - start) * (1.0f / STEPF)) + 2;
    seg_hi = min(seg_hi, iend);
    if (seg_lo >= seg_hi) {
        if (lane == 0) g_part[ray * NSEG + seg] = make_float4(0.0f, 0.0f, 0.0f, 1.0f);
        return;
    }
    const float seg_hi_f = (float)seg_hi - 0.5f;

    const float nrm = sqrtf(rdx * rdx + rdy * rdy + rdz * rdz);
    const float ds  = STEPF * nrm;

    const float SC = 63.5f / RADF;
    const float p0x = fmaf(start, rdx * SC, fmaf(rox, SC, 63.5f));
    const float p0y = fmaf(start, rdy * SC, fmaf(roy, SC, 63.5f));
    const float p0z = fmaf(start, rdz * SC, fmaf(roz, SC, 63.5f));
    const float svx = STEPF * rdx * SC, svy = STEPF * rdy * SC, svz = STEPF * rdz * SC;

    // SH basis
    const float x = rdx, y = rdy, z = rdz;
    float shv[9];
    shv[0] = 0.28209479177387814f;
    shv[1] = -0.4886025119029199f * y;
    shv[2] =  0.4886025119029199f * z;
    shv[3] = -0.4886025119029199f * x;
    shv[4] =  1.0925484305920792f * x * y;
    shv[5] = -1.0925484305920792f * y * z;
    shv[6] =  0.31539156525252005f * (2.0f * z * z - x * x - y * y);
    shv[7] = -1.0925484305920792f * x * z;
    shv[8] =  0.5462742152960396f * (x * x - y * y);

    __half2 sh_lo, sh_hi;
    if (l8 < 6) {
        const int k0 = (l8 & 1) * 4;
        sh_lo = __floats2half2_rn(shv[k0], shv[k0 + 1]);
        sh_hi = __floats2half2_rn(shv[k0 + 2], shv[k0 + 3]);
    } else if (l8 == 6) {
        sh_lo = __floats2half2_rn(shv[8], shv[8]);
        sh_hi = __floats2half2_rn(shv[8], 1.0f);
    } else {
        sh_lo = __floats2half2_rn(0.0f, 0.0f);
        sh_hi = sh_lo;
    }

    const uint2* __restrict__ gq = (const uint2*)g_grid2;

    float T = 1.0f;
    float acc = 0.0f;

    for (int i = seg_lo; i < seg_hi; i += 4) {
        const float fi = (float)i + qf;
        float ux = fmaf(fi, svx, p0x);
        float uy = fmaf(fi, svy, p0y);
        float uz = fmaf(fi, svz, p0z);
        const bool inb = (ux > 0.0f) & (ux < 127.0f) &
                         (uy > 0.0f) & (uy < 127.0f) &
                         (uz > 0.0f) & (uz < 127.0f) &
                         (fi < seg_hi_f);
        if (!inb) { ux = 1.0f; uy = 1.0f; uz = 1.0f; }

        const float flx = floorf(ux), fly = floorf(uy), flz = floorf(uz);
        const int ix = (int)flx, iy = (int)fly, iz = (int)flz;
        const float fx = ux - flx, fy = uy - fly, fz = uz - flz;

        const unsigned dxi = (ix < 127) ? 8u : 0u;
        const unsigned dyi = (iy < 127) ? (RESG * 8u) : 0u;
        const unsigned dzi = (iz < 127) ? (RESG * RESG * 8u) : 0u;
        const unsigned vb = ((unsigned)(iz * RESG + iy) * RESG + (unsigned)ix) * 8u
                            + (unsigned)l8;

        const uint2 u000 = __ldg(&gq[vb]);
        const uint2 u001 = __ldg(&gq[vb + dxi]);
        const uint2 u010 = __ldg(&gq[vb + dyi]);
        const uint2 u011 = __ldg(&gq[vb + dyi + dxi]);
        const uint2 u100 = __ldg(&gq[vb + dzi]);
        const uint2 u101 = __ldg(&gq[vb + dzi + dxi]);
        const uint2 u110 = __ldg(&gq[vb + dzi + dyi]);
        const uint2 u111 = __ldg(&gq[vb + dzi + dyi + dxi]);

        const float gx = 1.0f - fx, gy = 1.0f - fy, gz = 1.0f - fz;
        const float a00 = gz * gy, a01 = gz * fy, a10 = fz * gy, a11 = fz * fy;
        const __half2 w0 = __float2half2_rn(a00 * gx), w1 = __float2half2_rn(a00 * fx);
        const __half2 w2 = __float2half2_rn(a01 * gx), w3 = __float2half2_rn(a01 * fx);
        const __half2 w4 = __float2half2_rn(a10 * gx), w5 = __float2half2_rn(a10 * fx);
        const __half2 w6 = __float2half2_rn(a11 * gx), w7 = __float2half2_rn(a11 * fx);

#define H2(u) (*(const __half2*)&(u))
        __half2 alo = __hmul2(H2(u000.x), w0);
        __half2 ahi = __hmul2(H2(u000.y), w0);
        alo = __hfma2(H2(u001.x), w1, alo);  ahi = __hfma2(H2(u001.y), w1, ahi);
        alo = __hfma2(H2(u010.x), w2, alo);  ahi = __hfma2(H2(u010.y), w2, ahi);
        alo = __hfma2(H2(u011.x), w3, alo);  ahi = __hfma2(H2(u011.y), w3, ahi);
        alo = __hfma2(H2(u100.x), w4, alo);  ahi = __hfma2(H2(u100.y), w4, ahi);
        alo = __hfma2(H2(u101.x), w5, alo);  ahi = __hfma2(H2(u101.y), w5, ahi);
        alo = __hfma2(H2(u110.x), w6, alo);  ahi = __hfma2(H2(u110.y), w6, ahi);
        alo = __hfma2(H2(u111.x), w7, alo);  ahi = __hfma2(H2(u111.y), w7, ahi);
#undef H2

        // products with SH weights (lane6 kept per-element)
        const __half2 pl = __hmul2(alo, sh_lo);
        const __half2 ph = __hmul2(ahi, sh_hi);

        // per-lane dot (lanes 0..5): sum of 4 products
        const float2 fl = __half22float2(pl);
        const float2 fh = __half22float2(ph);
        const float p = (fl.x + fl.y) + (fh.x + fh.y);

        // broadcast lane6 regs within each quarter
        const unsigned u6lo = __shfl_sync(0xffffffffu, *(const unsigned*)&pl, 6, 8);
        const unsigned u6hi = __shfl_sync(0xffffffffu, *(const unsigned*)&ph, 6, 8);
        const float2 xlo = __half22float2(*(const __half2*)&u6lo);
        const float2 xhi = __half22float2(*(const __half2*)&u6hi);

        // pair sum: lanes 0/2/4 get color dot (k0..7 part)
        float r = p + __shfl_down_sync(0xffffffffu, p, 1, 8);
        float extra = 0.0f;
        if (l8 == 0) extra = xlo.x;
        else if (l8 == 2) extra = xlo.y;
        else if (l8 == 4) extra = xhi.x;
        r += extra;

        // sigma (exact through HMUL2 by 1.0)
        const float sigma = inb ? fmaxf(xhi.y, 0.0f) : 0.0f;
        const float e = __expf(-sigma * ds);

        // 4-way transmittance: butterfly prefix products across quarters
        const float f1  = __shfl_xor_sync(0xffffffffu, e, 8);
        const float ef1 = e * f1;
        const float f2v = __shfl_xor_sync(0xffffffffu, ef1, 16);
        float pre = (lane & 8) ? f1 : 1.0f;
        if (lane & 16) pre *= f2v;
        const float factor = T * pre * (1.0f - e);
        const float sgm = __frcp_rn(1.0f + __expf(-r));
        acc = fmaf(factor, sgm, acc);
        T = T * ef1 * f2v;
    }

    // sum quarters: lanes with same l8 combine
    float rsum = acc + __shfl_xor_sync(0xffffffffu, acc, 8);
    rsum += __shfl_xor_sync(0xffffffffu, rsum, 16);
    const float c0 = __shfl_sync(0xffffffffu, rsum, 0);
    const float c1 = __shfl_sync(0xffffffffu, rsum, 2);
    const float c2 = __shfl_sync(0xffffffffu, rsum, 4);
    if (lane == 0) g_part[ray * NSEG + seg] = make_float4(c0, c1, c2, T);
}

// ---------------------------------------------------------------------------
// Kernel 3: combine segment partials
// ---------------------------------------------------------------------------
__global__ void __launch_bounds__(128) combine_kernel(float* __restrict__ out) {
    const int r = blockIdx.x * blockDim.x + threadIdx.x;
    if (r >= NRAYS) return;
    float c0 = 0.0f, c1 = 0.0f, c2 = 0.0f, T = 1.0f;
#pragma unroll
    for (int s = 0; s < NSEG; ++s) {
        const float4 p = g_part[r * NSEG + s];
        c0 = fmaf(T, p.x, c0);
        c1 = fmaf(T, p.y, c1);
        c2 = fmaf(T, p.z, c2);
        T *= p.w;
    }
    out[r * 3 + 0] = c0 + T;
    out[r * 3 + 1] = c1 + T;
    out[r * 3 + 2] = c2 + T;
}

extern "C" void kernel_launch(void* const* d_in, const int* in_sizes, int n_in,
                              void* d_out, int out_size) {
    const float* rays_o = (const float*)d_in[0];
    const float* rays_d = (const float*)d_in[1];
    const float* data   = (const float*)d_in[2];
    float* out = (float*)d_out;

    xpose_kernel<<<RESG * RESG, 128>>>(data);
    march_kernel<<<NRAYS * NSEG / 4, 128>>>(rays_o, rays_d);
    combine_kernel<<<NRAYS / 128, 128>>>(out);
}